// round 17
// baseline (speedup 1.0000x reference)
#include <cuda_runtime.h>
#include <cuda_bf16.h>
#include <math.h>

// Problem constants: N=100000, E=1600000, G=1024, D=32, C=10
#define DD 32
#define CC 10
#define MAX_N 100352
#define MAX_E 1664000
#define MAX_G 2048

typedef unsigned long long u64;
typedef unsigned int u32;

// Scratch (alloc-free rule: __device__ globals)
// g_pair: per-node interleaved pair operand, 64 bf16 = 8 chunks of 16B:
//   chunk c: {first[4c..4c+3], second[4c..4c+3]}
//   resgated: (q,v) gathered from src ; film: (beta,gamma) read at dst
// g_single: per-node single operand, 32 bf16 (k for resgated, xl for film)
__device__ __align__(16) __nv_bfloat16 g_pair[MAX_N * 2 * DD];
__device__ __align__(16) __nv_bfloat16 g_single[MAX_N * DD];
__device__ float g_bufS[MAX_N * DD];   // skip path (fp32)
__device__ float g_bufH[MAX_N * DD];   // film skip output (fp32)
__device__ float g_bufA[MAX_N * DD];   // aggregation output (fp32)
__device__ float g_gsum[MAX_G * DD];
__device__ float g_gcnt[MAX_G];
// CSR by dst (built once per launch, reused by all 3 layers)
__device__ int g_cnt[MAX_N];     // in-degree
__device__ int g_off[MAX_N];     // exclusive prefix (segment start)
__device__ int g_cur[MAX_N];     // scatter cursor
__device__ int g_srt[MAX_E];     // src node of each edge, grouped by dst

// ---------------------------------------------------------------------------
__device__ __forceinline__ float sigmoidf_fast(float x) {
    return __frcp_rn(1.0f + __expf(-x));
}
__device__ __forceinline__ float2 bf2f(u32 w) {
    __nv_bfloat162 h = *reinterpret_cast<__nv_bfloat162*>(&w);
    return __bfloat1622float2(h);
}
__device__ __forceinline__ float4 ld_bf4(const __nv_bfloat16* base, int idx4) {
    uint2 r = __ldg(((const uint2*)base) + idx4);
    float2 fa = bf2f(r.x), fb = bf2f(r.y);
    return make_float4(fa.x, fa.y, fb.x, fb.y);
}
__device__ __forceinline__ u32 pack_bf2(float lo, float hi) {
    __nv_bfloat162 h = __floats2bfloat162_rn(lo, hi);
    return *reinterpret_cast<u32*>(&h);
}
__device__ __forceinline__ u32 f2tf32(float f) {
    u32 r;
    asm("cvt.rna.tf32.f32 %0, %1;" : "=r"(r) : "f"(f));
    return r;
}
__device__ __forceinline__ void mma_tf32(
    float& d0, float& d1, float& d2, float& d3,
    u32 a0, u32 a1, u32 a2, u32 a3, u32 b0, u32 b1,
    float c0, float c1, float c2, float c3)
{
    asm volatile(
        "mma.sync.aligned.m16n8k8.row.col.f32.tf32.tf32.f32 "
        "{%0,%1,%2,%3}, {%4,%5,%6,%7}, {%8,%9}, {%10,%11,%12,%13};"
        : "=f"(d0), "=f"(d1), "=f"(d2), "=f"(d3)
        : "r"(a0), "r"(a1), "r"(a2), "r"(a3), "r"(b0), "r"(b1),
          "f"(c0), "f"(c1), "f"(c2), "f"(c3));
}

// ---------------------------------------------------------------------------
// CSR construction
__global__ __launch_bounds__(256) void hist_kernel(
    const int* __restrict__ ei, int E)
{
    int e = blockIdx.x * blockDim.x + threadIdx.x;
    if (e >= E) return;
    atomicAdd(&g_cnt[__ldg(&ei[E + e])], 1);
}

// Single-block exclusive scan of g_cnt -> g_off (and g_cur copy).
__global__ __launch_bounds__(1024) void scan_kernel(int N)
{
    __shared__ int sdata[1024];
    int tid = threadIdx.x;
    int chunk = (N + 1023) / 1024;
    int start = tid * chunk;
    int end = min(start + chunk, N);
    int s = 0;
    for (int j = start; j < end; j++) s += g_cnt[j];
    sdata[tid] = s;
    __syncthreads();
    // Hillis-Steele inclusive scan
    for (int o = 1; o < 1024; o <<= 1) {
        int v = (tid >= o) ? sdata[tid - o] : 0;
        __syncthreads();
        sdata[tid] += v;
        __syncthreads();
    }
    int run = sdata[tid] - s;   // exclusive base for this chunk
    for (int j = start; j < end; j++) {
        g_off[j] = run;
        g_cur[j] = run;
        run += g_cnt[j];
    }
}

__global__ __launch_bounds__(256) void scatter_kernel(
    const int* __restrict__ ei, int E)
{
    int e = blockIdx.x * blockDim.x + threadIdx.x;
    if (e >= E) return;
    int s = __ldg(&ei[e]);
    int d = __ldg(&ei[E + e]);
    int pos = atomicAdd(&g_cur[d], 1);
    g_srt[pos] = s;
}

// ---------------------------------------------------------------------------
// Layer 1 node transform (F_IN = 1): single=k, pair=(q,v), S fp32
__global__ __launch_bounds__(256) void node1_kernel(
    const float* __restrict__ x, int N,
    const float* __restrict__ Wk, const float* __restrict__ bk,
    const float* __restrict__ Wq, const float* __restrict__ bq,
    const float* __restrict__ Wv, const float* __restrict__ bv,
    const float* __restrict__ Ws, const float* __restrict__ b)
{
    int t = blockIdx.x * blockDim.x + threadIdx.x;
    if (t >= N * DD) return;
    int i = t >> 5;
    int d = t & 31;
    float xv = __ldg(&x[i]);
    float k = fmaf(xv, __ldg(&Wk[d]), __ldg(&bk[d]));
    float q = fmaf(xv, __ldg(&Wq[d]), __ldg(&bq[d]));
    float v = fmaf(xv, __ldg(&Wv[d]), __ldg(&bv[d]));
    g_single[t] = __float2bfloat16(k);
    int pbase = i * 64 + (d >> 2) * 8 + (d & 3);
    g_pair[pbase]     = __float2bfloat16(q);
    g_pair[pbase + 4] = __float2bfloat16(v);
    g_bufS[t] = fmaf(xv, __ldg(&Ws[d]), __ldg(&b[d]));
}

// ---------------------------------------------------------------------------
// ResGated aggregation over CSR: octet (8 lanes) per node.
// agg[i] = sum_{s in nbrs(i)} sigmoid(k[i] + q[s]) * v[s]
__global__ __launch_bounds__(256) void agg_resgated_csr(int N)
{
    int gt = blockIdx.x * blockDim.x + threadIdx.x;
    int i = gt >> 3;
    if (i >= N) return;
    int c = gt & 7;
    float4 k = ld_bf4(g_single, i * 8 + c);
    int off = __ldg(&g_off[i]);
    int deg = __ldg(&g_cnt[i]);
    const uint4* pp = (const uint4*)g_pair;
    float4 acc = make_float4(0.0f, 0.0f, 0.0f, 0.0f);
    int j = 0;
    for (; j + 4 <= deg; j += 4) {
        int s0 = __ldg(&g_srt[off + j]);
        int s1 = __ldg(&g_srt[off + j + 1]);
        int s2 = __ldg(&g_srt[off + j + 2]);
        int s3 = __ldg(&g_srt[off + j + 3]);
        uint4 r0 = __ldg(pp + s0 * 8 + c);
        uint4 r1 = __ldg(pp + s1 * 8 + c);
        uint4 r2 = __ldg(pp + s2 * 8 + c);
        uint4 r3 = __ldg(pp + s3 * 8 + c);
#pragma unroll
        for (int u = 0; u < 4; u++) {
            uint4 r = (u == 0) ? r0 : (u == 1) ? r1 : (u == 2) ? r2 : r3;
            float2 q01 = bf2f(r.x), q23 = bf2f(r.y);
            float2 v01 = bf2f(r.z), v23 = bf2f(r.w);
            acc.x += sigmoidf_fast(k.x + q01.x) * v01.x;
            acc.y += sigmoidf_fast(k.y + q01.y) * v01.y;
            acc.z += sigmoidf_fast(k.z + q23.x) * v23.x;
            acc.w += sigmoidf_fast(k.w + q23.y) * v23.y;
        }
    }
    for (; j < deg; j++) {
        int s0 = __ldg(&g_srt[off + j]);
        uint4 r0 = __ldg(pp + s0 * 8 + c);
        float2 q01 = bf2f(r0.x), q23 = bf2f(r0.y);
        float2 v01 = bf2f(r0.z), v23 = bf2f(r0.w);
        acc.x += sigmoidf_fast(k.x + q01.x) * v01.x;
        acc.y += sigmoidf_fast(k.y + q01.y) * v01.y;
        acc.z += sigmoidf_fast(k.z + q23.x) * v23.x;
        acc.w += sigmoidf_fast(k.w + q23.y) * v23.y;
    }
    *(float4*)&g_bufA[i * DD + (c << 2)] = acc;
}

// ---------------------------------------------------------------------------
// FiLM aggregation over CSR: agg[i] = sum relu(gamma[i]*xl[s] + beta[i])
__global__ __launch_bounds__(256) void agg_film_csr(int N)
{
    int gt = blockIdx.x * blockDim.x + threadIdx.x;
    int i = gt >> 3;
    if (i >= N) return;
    int c = gt & 7;
    uint4 r = __ldg(((const uint4*)g_pair) + i * 8 + c);
    float2 b01 = bf2f(r.x), b23 = bf2f(r.y);
    float2 g01 = bf2f(r.z), g23 = bf2f(r.w);
    int off = __ldg(&g_off[i]);
    int deg = __ldg(&g_cnt[i]);
    float4 acc = make_float4(0.0f, 0.0f, 0.0f, 0.0f);
    int j = 0;
    for (; j + 4 <= deg; j += 4) {
        int s0 = __ldg(&g_srt[off + j]);
        int s1 = __ldg(&g_srt[off + j + 1]);
        int s2 = __ldg(&g_srt[off + j + 2]);
        int s3 = __ldg(&g_srt[off + j + 3]);
        float4 x0 = ld_bf4(g_single, s0 * 8 + c);
        float4 x1 = ld_bf4(g_single, s1 * 8 + c);
        float4 x2 = ld_bf4(g_single, s2 * 8 + c);
        float4 x3 = ld_bf4(g_single, s3 * 8 + c);
#pragma unroll
        for (int u = 0; u < 4; u++) {
            float4 xv = (u == 0) ? x0 : (u == 1) ? x1 : (u == 2) ? x2 : x3;
            acc.x += fmaxf(fmaf(g01.x, xv.x, b01.x), 0.0f);
            acc.y += fmaxf(fmaf(g01.y, xv.y, b01.y), 0.0f);
            acc.z += fmaxf(fmaf(g23.x, xv.z, b23.x), 0.0f);
            acc.w += fmaxf(fmaf(g23.y, xv.w, b23.y), 0.0f);
        }
    }
    for (; j < deg; j++) {
        int s0 = __ldg(&g_srt[off + j]);
        float4 x0 = ld_bf4(g_single, s0 * 8 + c);
        acc.x += fmaxf(fmaf(g01.x, x0.x, b01.x), 0.0f);
        acc.y += fmaxf(fmaf(g01.y, x0.y, b01.y), 0.0f);
        acc.z += fmaxf(fmaf(g23.x, x0.z, b23.x), 0.0f);
        acc.w += fmaxf(fmaf(g23.y, x0.w, b23.y), 0.0f);
    }
    *(float4*)&g_bufA[i * DD + (c << 2)] = acc;
}

// ---------------------------------------------------------------------------
// FiLM node transform via tensor cores (tf32, m16n8k8, 4 k-steps).
// Fused W_all [32 x 192]: Wlin | film beta(+b) | film gamma(+b) | Wls |
// fs beta | fs gamma. Epilogue: single=xl, pair=(beta,gamma), H fp32.
__global__ __launch_bounds__(128) void film_mma_kernel(
    int N,
    const float* __restrict__ Wlin, const float* __restrict__ Wfilm,
    const float* __restrict__ bfilm,
    const float* __restrict__ Wls, const float* __restrict__ Wfs)
{
    __shared__ u32 sh_h[16][33];
    __shared__ float sout[16][200];

    int tid = threadIdx.x;
    int lane = tid & 31;
    int warp = tid >> 5;
    int g = lane >> 2;
    int tq = lane & 3;
    int i0 = blockIdx.x * 16;

    auto getW = [&](int k, int c) -> float {
        if (c < 32)       return __ldg(&Wlin[k * 32 + c]);
        else if (c < 64)  return __ldg(&Wfilm[k * 64 + (c - 32)]);
        else if (c < 96)  return __ldg(&Wfilm[k * 64 + 32 + (c - 64)]);
        else if (c < 128) return __ldg(&Wls[k * 32 + (c - 96)]);
        else if (c < 160) return __ldg(&Wfs[k * 64 + (c - 128)]);
        else              return __ldg(&Wfs[k * 64 + 32 + (c - 160)]);
    };
    auto getB = [&](int c) -> float {
        if (c < 32)      return 0.0f;
        else if (c < 96) return __ldg(&bfilm[c - 32]);
        else             return 0.0f;
    };

    u32 bfr[6][4][2];
    float acc[6][4];
#pragma unroll
    for (int nt = 0; nt < 6; nt++) {
        int n0 = warp * 48 + nt * 8;
        int n = n0 + g;
#pragma unroll
        for (int ks = 0; ks < 4; ks++) {
            int k0 = 8 * ks;
            bfr[nt][ks][0] = f2tf32(getW(k0 + tq, n));
            bfr[nt][ks][1] = f2tf32(getW(k0 + tq + 4, n));
        }
        float b0 = getB(n0 + 2 * tq);
        float b1 = getB(n0 + 2 * tq + 1);
        acc[nt][0] = b0; acc[nt][1] = b1; acc[nt][2] = b0; acc[nt][3] = b1;
    }

    // --- Stage h = relu(A + S) as tf32 words ---
    {
        int m = tid >> 3;
        int f0 = (tid & 7) << 2;
        int node = i0 + m;
        float4 a = make_float4(0, 0, 0, 0), s = make_float4(0, 0, 0, 0);
        if (node < N) {
            a = *(const float4*)&g_bufA[node * DD + f0];
            s = *(const float4*)&g_bufS[node * DD + f0];
        }
        sh_h[m][f0 + 0] = f2tf32(fmaxf(a.x + s.x, 0.0f));
        sh_h[m][f0 + 1] = f2tf32(fmaxf(a.y + s.y, 0.0f));
        sh_h[m][f0 + 2] = f2tf32(fmaxf(a.z + s.z, 0.0f));
        sh_h[m][f0 + 3] = f2tf32(fmaxf(a.w + s.w, 0.0f));
    }
    __syncthreads();

#pragma unroll
    for (int ks = 0; ks < 4; ks++) {
        int k0 = 8 * ks;
        u32 a0 = sh_h[g][k0 + tq];
        u32 a1 = sh_h[g + 8][k0 + tq];
        u32 a2 = sh_h[g][k0 + tq + 4];
        u32 a3 = sh_h[g + 8][k0 + tq + 4];
#pragma unroll
        for (int nt = 0; nt < 6; nt++) {
            mma_tf32(acc[nt][0], acc[nt][1], acc[nt][2], acc[nt][3],
                     a0, a1, a2, a3, bfr[nt][ks][0], bfr[nt][ks][1],
                     acc[nt][0], acc[nt][1], acc[nt][2], acc[nt][3]);
        }
    }

#pragma unroll
    for (int nt = 0; nt < 6; nt++) {
        int c = warp * 48 + nt * 8 + 2 * tq;
        sout[g][c] = acc[nt][0];
        sout[g][c + 1] = acc[nt][1];
        sout[g + 8][c] = acc[nt][2];
        sout[g + 8][c + 1] = acc[nt][3];
    }
    __syncthreads();

    {
        int m = tid >> 3;
        int f0 = (tid & 7) << 2;
        int node = i0 + m;
        if (node < N) {
            float4 xl = *(const float4*)&sout[m][f0];
            float4 be = *(const float4*)&sout[m][32 + f0];
            float4 ga = *(const float4*)&sout[m][64 + f0];
            float4 ls = *(const float4*)&sout[m][96 + f0];
            float4 bs = *(const float4*)&sout[m][128 + f0];
            float4 gs = *(const float4*)&sout[m][160 + f0];
            int t = node * DD + f0;
            *reinterpret_cast<uint2*>(&g_single[t]) =
                make_uint2(pack_bf2(xl.x, xl.y), pack_bf2(xl.z, xl.w));
            uint4 pc = make_uint4(pack_bf2(be.x, be.y), pack_bf2(be.z, be.w),
                                  pack_bf2(ga.x, ga.y), pack_bf2(ga.z, ga.w));
            ((uint4*)g_pair)[node * 8 + (f0 >> 2)] = pc;
            float4 h;
            h.x = fmaxf(fmaf(gs.x, ls.x, bs.x), 0.0f);
            h.y = fmaxf(fmaf(gs.y, ls.y, bs.y), 0.0f);
            h.z = fmaxf(fmaf(gs.z, ls.z, bs.z), 0.0f);
            h.w = fmaxf(fmaf(gs.w, ls.w, bs.w), 0.0f);
            *(float4*)&g_bufH[t] = h;
        }
    }
}

// ---------------------------------------------------------------------------
// Layer-3 node transform via tensor cores (tf32). Warp w = matrix w.
// Input h2 = relu(fma(A, 1/max(deg,1), H)); epilogue single=k, pair=(q,v).
__global__ __launch_bounds__(128) void node3_mma_kernel(
    int N,
    const float* __restrict__ Wk, const float* __restrict__ bk,
    const float* __restrict__ Wq, const float* __restrict__ bq,
    const float* __restrict__ Wv, const float* __restrict__ bv,
    const float* __restrict__ Ws, const float* __restrict__ b)
{
    __shared__ u32 sh_h[16][33];
    __shared__ float sout[16][136];

    int tid = threadIdx.x;
    int lane = tid & 31;
    int warp = tid >> 5;
    int g = lane >> 2;
    int tq = lane & 3;
    int i0 = blockIdx.x * 16;

    const float* Wsel = (warp == 0) ? Wk : (warp == 1) ? Wq : (warp == 2) ? Wv : Ws;
    const float* bsel = (warp == 0) ? bk : (warp == 1) ? bq : (warp == 2) ? bv : b;

    u32 bfr[4][4][2];
    float acc[4][4];
#pragma unroll
    for (int nt = 0; nt < 4; nt++) {
        int nc = nt * 8 + g;
#pragma unroll
        for (int ks = 0; ks < 4; ks++) {
            int k0 = 8 * ks;
            bfr[nt][ks][0] = f2tf32(__ldg(&Wsel[(k0 + tq) * 32 + nc]));
            bfr[nt][ks][1] = f2tf32(__ldg(&Wsel[(k0 + tq + 4) * 32 + nc]));
        }
        float b0 = __ldg(&bsel[nt * 8 + 2 * tq]);
        float b1 = __ldg(&bsel[nt * 8 + 2 * tq + 1]);
        acc[nt][0] = b0; acc[nt][1] = b1; acc[nt][2] = b0; acc[nt][3] = b1;
    }

    {
        int m = tid >> 3;
        int f0 = (tid & 7) << 2;
        int node = i0 + m;
        float4 a = make_float4(0, 0, 0, 0), hh = make_float4(0, 0, 0, 0);
        float inv = 1.0f;
        if (node < N) {
            inv = __frcp_rn(fmaxf((float)__ldg(&g_cnt[node]), 1.0f));
            a = *(const float4*)&g_bufA[node * DD + f0];
            hh = *(const float4*)&g_bufH[node * DD + f0];
        }
        sh_h[m][f0 + 0] = f2tf32(fmaxf(fmaf(a.x, inv, hh.x), 0.0f));
        sh_h[m][f0 + 1] = f2tf32(fmaxf(fmaf(a.y, inv, hh.y), 0.0f));
        sh_h[m][f0 + 2] = f2tf32(fmaxf(fmaf(a.z, inv, hh.z), 0.0f));
        sh_h[m][f0 + 3] = f2tf32(fmaxf(fmaf(a.w, inv, hh.w), 0.0f));
    }
    __syncthreads();

#pragma unroll
    for (int ks = 0; ks < 4; ks++) {
        int k0 = 8 * ks;
        u32 a0 = sh_h[g][k0 + tq];
        u32 a1 = sh_h[g + 8][k0 + tq];
        u32 a2 = sh_h[g][k0 + tq + 4];
        u32 a3 = sh_h[g + 8][k0 + tq + 4];
#pragma unroll
        for (int nt = 0; nt < 4; nt++) {
            mma_tf32(acc[nt][0], acc[nt][1], acc[nt][2], acc[nt][3],
                     a0, a1, a2, a3, bfr[nt][ks][0], bfr[nt][ks][1],
                     acc[nt][0], acc[nt][1], acc[nt][2], acc[nt][3]);
        }
    }

#pragma unroll
    for (int nt = 0; nt < 4; nt++) {
        int c = warp * 32 + nt * 8 + 2 * tq;
        sout[g][c] = acc[nt][0];
        sout[g][c + 1] = acc[nt][1];
        sout[g + 8][c] = acc[nt][2];
        sout[g + 8][c + 1] = acc[nt][3];
    }
    __syncthreads();

    {
        int m = tid >> 3;
        int f0 = (tid & 7) << 2;
        int node = i0 + m;
        if (node < N) {
            float4 kk = *(const float4*)&sout[m][f0];
            float4 qq = *(const float4*)&sout[m][32 + f0];
            float4 vv = *(const float4*)&sout[m][64 + f0];
            float4 ss = *(const float4*)&sout[m][96 + f0];
            int t = node * DD + f0;
            *reinterpret_cast<uint2*>(&g_single[t]) =
                make_uint2(pack_bf2(kk.x, kk.y), pack_bf2(kk.z, kk.w));
            uint4 pc = make_uint4(pack_bf2(qq.x, qq.y), pack_bf2(qq.z, qq.w),
                                  pack_bf2(vv.x, vv.y), pack_bf2(vv.z, vv.w));
            ((uint4*)g_pair)[node * 8 + (f0 >> 2)] = pc;
            *(float4*)&g_bufS[t] = ss;
        }
    }
}

// ---------------------------------------------------------------------------
// Pool: h3 = agg + skip; gsum[batch[i]] += h3, 8 lanes per node
__global__ __launch_bounds__(256) void pool_kernel(
    const int* __restrict__ batch, int N)
{
    int gt = blockIdx.x * blockDim.x + threadIdx.x;
    int i = gt >> 3;
    if (i >= N) return;
    int c = (gt & 7) << 2;
    int t = i * DD + c;
    float4 a = *(const float4*)&g_bufA[t];
    float4 s = *(const float4*)&g_bufS[t];
    float4 r;
    r.x = a.x + s.x; r.y = a.y + s.y; r.z = a.z + s.z; r.w = a.w + s.w;
    int bgr = __ldg(&batch[i]);
    asm volatile("red.global.add.v4.f32 [%0], {%1,%2,%3,%4};"
                 :: "l"(&g_gsum[bgr * DD + c]),
                    "f"(r.x), "f"(r.y), "f"(r.z), "f"(r.w) : "memory");
    if ((gt & 7) == 0) atomicAdd(&g_gcnt[bgr], 1.0f);
}

// ---------------------------------------------------------------------------
__global__ __launch_bounds__(128) void final_kernel(
    const float* __restrict__ linW, const float* __restrict__ linb,
    float* __restrict__ out, int G)
{
    __shared__ float sW[DD * CC];
    __shared__ float sb[CC];
    for (int j = threadIdx.x; j < DD * CC; j += blockDim.x) sW[j] = linW[j];
    if (threadIdx.x < CC) sb[threadIdx.x] = linb[threadIdx.x];
    __syncthreads();

    int g = blockIdx.x * blockDim.x + threadIdx.x;
    if (g >= G) return;
    float inv = __frcp_rn(fmaxf(g_gcnt[g], 1.0f));
    float acc[CC];
#pragma unroll
    for (int c = 0; c < CC; c++) acc[c] = sb[c];
#pragma unroll
    for (int j = 0; j < DD; j++) {
        float m = g_gsum[g * DD + j] * inv;
#pragma unroll
        for (int c = 0; c < CC; c++) acc[c] = fmaf(m, sW[j * CC + c], acc[c]);
    }
#pragma unroll
    for (int c = 0; c < CC; c++) out[g * CC + c] = acc[c];
}

// ---------------------------------------------------------------------------
static inline int nblk(long long threads, int tpb) {
    return (int)((threads + tpb - 1) / tpb);
}

extern "C" void kernel_launch(void* const* d_in, const int* in_sizes, int n_in,
                              void* d_out, int out_size)
{
    const float* x     = (const float*)d_in[0];
    const int*   ei    = (const int*)d_in[1];
    const int*   batch = (const int*)d_in[2];
    const float* c1_Wk = (const float*)d_in[4];
    const float* c1_bk = (const float*)d_in[5];
    const float* c1_Wq = (const float*)d_in[6];
    const float* c1_bq = (const float*)d_in[7];
    const float* c1_Wv = (const float*)d_in[8];
    const float* c1_bv = (const float*)d_in[9];
    const float* c1_Ws = (const float*)d_in[10];
    const float* c1_b  = (const float*)d_in[11];
    const float* c2_Wlin  = (const float*)d_in[12];
    const float* c2_Wfilm = (const float*)d_in[13];
    const float* c2_bfilm = (const float*)d_in[14];
    const float* c2_Wls   = (const float*)d_in[15];
    const float* c2_Wfs   = (const float*)d_in[16];
    const float* c3_Wk = (const float*)d_in[17];
    const float* c3_bk = (const float*)d_in[18];
    const float* c3_Wq = (const float*)d_in[19];
    const float* c3_bq = (const float*)d_in[20];
    const float* c3_Wv = (const float*)d_in[21];
    const float* c3_bv = (const float*)d_in[22];
    const float* c3_Ws = (const float*)d_in[23];
    const float* c3_b  = (const float*)d_in[24];
    const float* linW  = (const float*)d_in[25];
    const float* linb  = (const float*)d_in[26];
    float* out = (float*)d_out;

    int N = in_sizes[0];
    int E = in_sizes[1] / 2;
    int G = out_size / CC;

    void *pCnt, *pGs, *pGc;
    cudaGetSymbolAddress(&pCnt, g_cnt);
    cudaGetSymbolAddress(&pGs,  g_gsum);
    cudaGetSymbolAddress(&pGc,  g_gcnt);

    const int TPB = 256;
    long long NT = (long long)N * DD;
    long long N8 = (long long)N * 8;
    int TILES = (N + 15) / 16;

    // ---- Build dst-sorted CSR once (reused by all 3 layers) ----
    cudaMemsetAsync(pCnt, 0, (size_t)N * sizeof(int));
    hist_kernel<<<nblk(E, TPB), TPB>>>(ei, E);
    scan_kernel<<<1, 1024>>>(N);
    scatter_kernel<<<nblk(E, TPB), TPB>>>(ei, E);

    // ---- Layer 1: ResGated(1 -> 32) ----
    node1_kernel<<<nblk(NT, TPB), TPB>>>(x, N, c1_Wk, c1_bk, c1_Wq, c1_bq,
                                         c1_Wv, c1_bv, c1_Ws, c1_b);
    agg_resgated_csr<<<nblk(N8, TPB), TPB>>>(N);

    // ---- Layer 2: FiLM(32 -> 32) ----
    film_mma_kernel<<<TILES, 128>>>(N, c2_Wlin, c2_Wfilm, c2_bfilm,
                                    c2_Wls, c2_Wfs);
    agg_film_csr<<<nblk(N8, TPB), TPB>>>(N);

    // ---- Layer 3: ResGated(32 -> 32) ----
    node3_mma_kernel<<<TILES, 128>>>(N, c3_Wk, c3_bk, c3_Wq, c3_bq,
                                     c3_Wv, c3_bv, c3_Ws, c3_b);
    agg_resgated_csr<<<nblk(N8, TPB), TPB>>>(N);

    // ---- Global mean pool + classifier ----
    cudaMemsetAsync(pGs, 0, (size_t)G * DD * sizeof(float));
    cudaMemsetAsync(pGc, 0, (size_t)G * sizeof(float));
    pool_kernel<<<nblk(N8, TPB), TPB>>>(batch, N);
    final_kernel<<<nblk(G, 128), 128>>>(linW, linb, out, G);
}